// round 6
// baseline (speedup 1.0000x reference)
#include <cuda_runtime.h>
#include <cuda_fp16.h>
#include <cstdint>

// Problem: out[b,k] = sum_ij X[b,ij] * W[ij,k];  B=512, ij=1M, k=128
#define IJ_DIM   1048576
#define B_DIM    512
#define K_OUT    128
#define M_TILE   128
#define KR_TILE  64
#define SPLITK   36
#define K_TILES_TOTAL (IJ_DIM / KR_TILE)      // 16384
#define NTHREADS 256
#define STAGE_BYTES 32768                      // A half 16K + B half 16K
#define SMEM_BYTES  (2 * STAGE_BYTES)

// split-K partials [SPLITK][B_DIM][K_OUT] (~9.4 MB device scratch, no allocs)
__device__ float g_partial[(size_t)SPLITK * B_DIM * K_OUT];

__device__ __forceinline__ uint32_t smem_u32(const void* p) {
    uint32_t a;
    asm("{ .reg .u64 t; cvta.to.shared.u64 t, %1; cvt.u32.u64 %0, t; }" : "=r"(a) : "l"(p));
    return a;
}
__device__ __forceinline__ uint32_t packh2(float f0, float f1) {
    __half2 h = __floats2half2_rn(f0, f1);
    return *reinterpret_cast<uint32_t*>(&h);
}
__device__ __forceinline__ void ldsm_x4(uint32_t& r0, uint32_t& r1, uint32_t& r2, uint32_t& r3,
                                        uint32_t addr) {
    asm volatile("ldmatrix.sync.aligned.m8n8.x4.shared.b16 {%0,%1,%2,%3}, [%4];"
                 : "=r"(r0), "=r"(r1), "=r"(r2), "=r"(r3) : "r"(addr));
}
__device__ __forceinline__ void ldsm_x4_t(uint32_t& r0, uint32_t& r1, uint32_t& r2, uint32_t& r3,
                                          uint32_t addr) {
    asm volatile("ldmatrix.sync.aligned.m8n8.x4.trans.shared.b16 {%0,%1,%2,%3}, [%4];"
                 : "=r"(r0), "=r"(r1), "=r"(r2), "=r"(r3) : "r"(addr));
}
__device__ __forceinline__ void mma16816(float* c, const uint32_t* a, const uint32_t* b) {
    asm volatile(
        "mma.sync.aligned.m16n8k16.row.col.f32.f16.f16.f32 "
        "{%0,%1,%2,%3}, {%4,%5,%6,%7}, {%8,%9}, {%0,%1,%2,%3};"
        : "+f"(c[0]), "+f"(c[1]), "+f"(c[2]), "+f"(c[3])
        : "r"(a[0]), "r"(a[1]), "r"(a[2]), "r"(a[3]), "r"(b[0]), "r"(b[1]));
}

__global__ void __launch_bounds__(NTHREADS, 1)
gemm_splitk_kernel(const float* __restrict__ X, const float* __restrict__ W)
{
    extern __shared__ __align__(1024) char smem[];
    const int tid  = threadIdx.x;
    const int lane = tid & 31;
    const int wid  = tid >> 5;

    const int mtile = blockIdx.x & 3;
    const int chunk = blockIdx.x >> 2;
    // distribute 16384 k-tiles over 36 chunks: first 4 get 456, rest 455
    const int base_tile = chunk * 455 + (chunk < 4 ? chunk : 4);
    const int cnt       = 455 + (chunk < 4 ? 1 : 0);
    const size_t mbase  = (size_t)mtile * M_TILE;
    const size_t kb0    = (size_t)base_tile * KR_TILE;

    const uint32_t smem_base = smem_u32(smem);

    // ---- load mappings (coalesced float4) ----
    // A: 128 rows x 64 k-cols fp32. thread: row = tid>>3 (+32p), 8 consecutive cols at (tid&7)*8
    const int ar_row = tid >> 3;          // 0..31
    const int ar_c8  = (tid & 7) * 8;     // 0..56
    // B (W chunk): 64 k-rows x 128 n. thread: k = tid>>5 (+8p), 4 consecutive n at (tid&31)*4
    const int br_k  = tid >> 5;           // 0..7
    const int br_n4 = (tid & 31) * 4;     // 0..124

    // ---- swizzled store offsets (constant per thread) ----
    // A smem: [m][64 half] 128B rows, chunk(16B) index XOR (row&7)
    const uint32_t a_st_c = (uint32_t)(((tid & 7) ^ (ar_row & 7)) & 7) * 16;
    // B smem: [k][128 half] 256B rows, two 128B halves swizzled independently by (k&7)=br_k
    const uint32_t b_st_c = (uint32_t)((br_n4 & 64) ? 128 : 0)
                          + (uint32_t)(((((br_n4 & 63) >> 3) ^ br_k) & 7) * 16)
                          + (uint32_t)((br_n4 & 7) * 2);

    // ---- warp compute tile: 4x2 warps, each 32(m) x 64(n) ----
    const int m0w = (wid & 3) * 32;
    const int n0w = (wid >> 2) * 64;

    // ldmatrix lane-local terms
    const int lrow  = (lane & 7) + ((lane >> 3) & 1) * 8;  // row within 16-block
    const int lksel = lane >> 4;                           // 0/1 -> +8 cols
    const int lnsel = (lane >> 4) * 8;                     // B: +8 n

    float acc[2][8][4];
    #pragma unroll
    for (int i = 0; i < 2; i++)
        #pragma unroll
        for (int j = 0; j < 8; j++)
            #pragma unroll
            for (int c = 0; c < 4; c++) acc[i][j][c] = 0.f;

    float4 ar[8], wr[8];

    auto load_regs = [&](int t) {
        const size_t kb = kb0 + (size_t)t * KR_TILE;
        #pragma unroll
        for (int p = 0; p < 4; p++) {
            const float* xp = X + (mbase + p * 32 + ar_row) * (size_t)IJ_DIM + kb + ar_c8;
            ar[p * 2]     = *reinterpret_cast<const float4*>(xp);
            ar[p * 2 + 1] = *reinterpret_cast<const float4*>(xp + 4);
        }
        #pragma unroll
        for (int p = 0; p < 8; p++)
            wr[p] = *reinterpret_cast<const float4*>(W + (kb + p * 8 + br_k) * (size_t)K_OUT + br_n4);
    };

    auto store_tile = [&](int buf) {
        char* As = smem + buf * STAGE_BYTES;
        char* Bs = As + 16384;
        #pragma unroll
        for (int p = 0; p < 4; p++) {
            const float* f = reinterpret_cast<const float*>(&ar[p * 2]);
            uint4 v;
            v.x = packh2(f[0], f[1]); v.y = packh2(f[2], f[3]);
            v.z = packh2(f[4], f[5]); v.w = packh2(f[6], f[7]);
            *reinterpret_cast<uint4*>(As + (uint32_t)(p * 32 + ar_row) * 128 + a_st_c) = v;
        }
        #pragma unroll
        for (int p = 0; p < 8; p++) {
            uint2 v;
            v.x = packh2(wr[p].x, wr[p].y); v.y = packh2(wr[p].z, wr[p].w);
            *reinterpret_cast<uint2*>(Bs + (uint32_t)(p * 8 + br_k) * 256 + b_st_c) = v;
        }
    };

    auto compute = [&](int buf) {
        const uint32_t As = smem_base + buf * STAGE_BYTES;
        const uint32_t Bs = As + 16384;
        #pragma unroll
        for (int ks = 0; ks < 4; ks++) {
            uint32_t a[2][4];
            #pragma unroll
            for (int mi = 0; mi < 2; mi++) {
                const int row = m0w + mi * 16 + lrow;
                const uint32_t addr = As + (uint32_t)row * 128
                    + (uint32_t)((((ks * 2 + lksel) ^ (lrow & 7)) & 7) * 16);
                ldsm_x4(a[mi][0], a[mi][1], a[mi][2], a[mi][3], addr);
            }
            uint32_t b[8][2];
            #pragma unroll
            for (int j = 0; j < 4; j++) {
                const int k = ks * 16 + lrow;
                const int n = n0w + j * 16 + lnsel;
                const uint32_t addr = Bs + (uint32_t)k * 256
                    + (uint32_t)((n & 64) ? 128 : 0)
                    + (uint32_t)(((((n & 63) >> 3) ^ (k & 7)) & 7) * 16);
                ldsm_x4_t(b[2 * j][0], b[2 * j][1], b[2 * j + 1][0], b[2 * j + 1][1], addr);
            }
            #pragma unroll
            for (int mi = 0; mi < 2; mi++)
                #pragma unroll
                for (int nj = 0; nj < 8; nj++)
                    mma16816(acc[mi][nj], a[mi], b[nj]);
        }
    };

    // prologue
    load_regs(0);
    store_tile(0);
    __syncthreads();

    #pragma unroll 1
    for (int t = 0; t < cnt; t++) {
        const bool more = (t + 1 < cnt);
        if (more) load_regs(t + 1);       // LDGs overlap the MMAs below
        compute(t & 1);
        if (more) store_tile((t + 1) & 1); // writes the buffer freed at last sync
        __syncthreads();
    }

    // epilogue: write split-K partials (deterministic)
    const int row0 = lane >> 2;
    const int col0 = (lane & 3) * 2;
    float* dst = &g_partial[(size_t)chunk * B_DIM * K_OUT];
    #pragma unroll
    for (int mi = 0; mi < 2; mi++) {
        #pragma unroll
        for (int nj = 0; nj < 8; nj++) {
            const size_t m = mbase + m0w + mi * 16 + row0;
            const int n = n0w + nj * 8 + col0;
            float2 v0 = make_float2(acc[mi][nj][0], acc[mi][nj][1]);
            float2 v1 = make_float2(acc[mi][nj][2], acc[mi][nj][3]);
            *reinterpret_cast<float2*>(dst + m * K_OUT + n) = v0;
            *reinterpret_cast<float2*>(dst + (m + 8) * K_OUT + n) = v1;
        }
    }
}

__global__ void reduce_kernel(float* __restrict__ out) {
    const int idx = blockIdx.x * blockDim.x + threadIdx.x;  // < 65536
    float s = 0.f;
    #pragma unroll
    for (int c = 0; c < SPLITK; c++)
        s += g_partial[(size_t)c * (B_DIM * K_OUT) + idx];
    out[idx] = s;
}

extern "C" void kernel_launch(void* const* d_in, const int* in_sizes, int n_in,
                              void* d_out, int out_size) {
    const float* X = (const float*)d_in[0];
    const float* W = (const float*)d_in[1];
    float* out = (float*)d_out;

    cudaFuncSetAttribute(gemm_splitk_kernel,
                         cudaFuncAttributeMaxDynamicSharedMemorySize, SMEM_BYTES);
    gemm_splitk_kernel<<<SPLITK * (B_DIM / M_TILE), NTHREADS, SMEM_BYTES>>>(X, W);
    reduce_kernel<<<(B_DIM * K_OUT) / 256, 256>>>(out);
}

// round 7
// speedup vs baseline: 1.1275x; 1.1275x over previous
#include <cuda_runtime.h>
#include <cuda_fp16.h>
#include <cstdint>

// Problem: out[b,k] = sum_ij X[b,ij] * W[ij,k];  B=512, ij=1M, k=128
#define IJ_DIM   1048576
#define B_DIM    512
#define K_OUT    128
#define M_TILE   256
#define KR_TILE  64
#define SPLITK   72
#define K_TILES_TOTAL (IJ_DIM / KR_TILE)      // 16384
#define NTHREADS 256
// A fp16 tile 256x64 = 32KB, B fp16 64x128 = 16KB
#define STAGE_BYTES 49152
#define SMEM_BYTES  (2 * STAGE_BYTES)         // 96KB double buffered

// split-K partials [SPLITK][B_DIM][K_OUT] (~18.9 MB device scratch, no allocs)
__device__ float g_partial[(size_t)SPLITK * B_DIM * K_OUT];

__device__ __forceinline__ uint32_t smem_u32(const void* p) {
    uint32_t a;
    asm("{ .reg .u64 t; cvta.to.shared.u64 t, %1; cvt.u32.u64 %0, t; }" : "=r"(a) : "l"(p));
    return a;
}
__device__ __forceinline__ uint32_t packh2(float f0, float f1) {
    __half2 h = __floats2half2_rn(f0, f1);
    return *reinterpret_cast<uint32_t*>(&h);
}
__device__ __forceinline__ void ldsm_x4(uint32_t& r0, uint32_t& r1, uint32_t& r2, uint32_t& r3,
                                        uint32_t addr) {
    asm volatile("ldmatrix.sync.aligned.m8n8.x4.shared.b16 {%0,%1,%2,%3}, [%4];"
                 : "=r"(r0), "=r"(r1), "=r"(r2), "=r"(r3) : "r"(addr));
}
__device__ __forceinline__ void ldsm_x4_t(uint32_t& r0, uint32_t& r1, uint32_t& r2, uint32_t& r3,
                                          uint32_t addr) {
    asm volatile("ldmatrix.sync.aligned.m8n8.x4.trans.shared.b16 {%0,%1,%2,%3}, [%4];"
                 : "=r"(r0), "=r"(r1), "=r"(r2), "=r"(r3) : "r"(addr));
}
__device__ __forceinline__ void mma16816(float* c, const uint32_t* a, const uint32_t* b) {
    asm volatile(
        "mma.sync.aligned.m16n8k16.row.col.f32.f16.f16.f32 "
        "{%0,%1,%2,%3}, {%4,%5,%6,%7}, {%8,%9}, {%0,%1,%2,%3};"
        : "+f"(c[0]), "+f"(c[1]), "+f"(c[2]), "+f"(c[3])
        : "r"(a[0]), "r"(a[1]), "r"(a[2]), "r"(a[3]), "r"(b[0]), "r"(b[1]));
}

__global__ void __launch_bounds__(NTHREADS, 1)
gemm_splitk_kernel(const float* __restrict__ X, const float* __restrict__ W)
{
    extern __shared__ __align__(1024) char smem[];
    const int tid  = threadIdx.x;
    const int lane = tid & 31;
    const int wid  = tid >> 5;

    const int mtile = blockIdx.x & 1;
    const int chunk = blockIdx.x >> 1;
    // 16384 k-tiles over 72 chunks: first 40 get 228, rest 227
    const int base_tile = chunk * 227 + (chunk < 40 ? chunk : 40);
    const int cnt       = 227 + (chunk < 40 ? 1 : 0);
    const size_t mbase  = (size_t)mtile * M_TILE;
    const size_t kb0    = (size_t)base_tile * KR_TILE;

    const uint32_t smem_base = smem_u32(smem);

    // ---- load mappings (coalesced) ----
    // A: 256 rows x 64 k-cols fp32; thread covers row (p*32 + tid>>3), 8 cols at (tid&7)*8
    const int ar_row = tid >> 3;          // 0..31
    const int ar_c8  = (tid & 7) * 8;     // 0..56
    // B: 64 k-rows x 128 n fp32; warp w covers full row (p*8 + wid), lane 4 n at lane*4
    const int br_k  = wid;                // 0..7
    const int br_n4 = lane * 4;           // 0..124

    // ---- swizzled store offsets ----
    // A smem: [m][64 half] 128B rows, 16B-chunk XOR (row&7)
    const uint32_t a_st_c = (uint32_t)(((tid & 7) ^ (ar_row & 7)) & 7) * 16;
    // B smem: [k][128 half] 256B rows, two 128B halves swizzled by k&7
    const uint32_t b_st_c = (uint32_t)((br_n4 & 64) ? 128 : 0)
                          + (uint32_t)(((((br_n4 & 63) >> 3) ^ br_k) & 7) * 16)
                          + (uint32_t)((br_n4 & 7) * 2);

    // ---- warp compute tile: 4(m) x 2(n) warps, each 64m x 64n ----
    const int m0w = (wid & 3) * 64;
    const int n0w = (wid >> 2) * 64;

    const int lrow  = (lane & 7) + ((lane >> 3) & 1) * 8;
    const int lksel = lane >> 4;
    const int lnsel = (lane >> 4) * 8;

    float acc[4][8][4];
    #pragma unroll
    for (int i = 0; i < 4; i++)
        #pragma unroll
        for (int j = 0; j < 8; j++)
            #pragma unroll
            for (int c = 0; c < 4; c++) acc[i][j][c] = 0.f;

    float4 ar[8];   // A half: 4 row-passes x 2 float4
    float4 wr[4];   // B half: 4 k-row passes x 1 float4

    auto load_A_half = [&](int t, int h) {
        const size_t kb = kb0 + (size_t)t * KR_TILE;
        #pragma unroll
        for (int p = 0; p < 4; p++) {
            const float* xp = X + (mbase + (h * 4 + p) * 32 + ar_row) * (size_t)IJ_DIM + kb + ar_c8;
            ar[p * 2]     = *reinterpret_cast<const float4*>(xp);
            ar[p * 2 + 1] = *reinterpret_cast<const float4*>(xp + 4);
        }
    };
    auto load_B_half = [&](int t, int h) {
        const size_t kb = kb0 + (size_t)t * KR_TILE;
        #pragma unroll
        for (int p = 0; p < 4; p++)
            wr[p] = *reinterpret_cast<const float4*>(
                W + (kb + (h * 4 + p) * 8 + br_k) * (size_t)K_OUT + br_n4);
    };
    auto store_A_half = [&](int buf, int h) {
        char* As = smem + buf * STAGE_BYTES;
        #pragma unroll
        for (int p = 0; p < 4; p++) {
            const float* f = reinterpret_cast<const float*>(&ar[p * 2]);
            uint4 v;
            v.x = packh2(f[0], f[1]); v.y = packh2(f[2], f[3]);
            v.z = packh2(f[4], f[5]); v.w = packh2(f[6], f[7]);
            *reinterpret_cast<uint4*>(
                As + (uint32_t)((h * 4 + p) * 32 + ar_row) * 128 + a_st_c) = v;
        }
    };
    auto store_B_half = [&](int buf, int h) {
        char* Bs = smem + buf * STAGE_BYTES + 32768;
        #pragma unroll
        for (int p = 0; p < 4; p++) {
            uint2 v;
            v.x = packh2(wr[p].x, wr[p].y); v.y = packh2(wr[p].z, wr[p].w);
            *reinterpret_cast<uint2*>(
                Bs + (uint32_t)((h * 4 + p) * 8 + br_k) * 256 + b_st_c) = v;
        }
    };

    auto compute1 = [&](int buf, int ks) {
        const uint32_t As = smem_base + buf * STAGE_BYTES;
        const uint32_t Bs = As + 32768;
        uint32_t a[4][4];
        #pragma unroll
        for (int mi = 0; mi < 4; mi++) {
            const int row = m0w + mi * 16 + lrow;
            const uint32_t addr = As + (uint32_t)row * 128
                + (uint32_t)((((ks * 2 + lksel) ^ (lrow & 7)) & 7) * 16);
            ldsm_x4(a[mi][0], a[mi][1], a[mi][2], a[mi][3], addr);
        }
        uint32_t b[8][2];
        #pragma unroll
        for (int j = 0; j < 4; j++) {
            const int k = ks * 16 + lrow;
            const int n = n0w + j * 16 + lnsel;
            const uint32_t addr = Bs + (uint32_t)k * 256
                + (uint32_t)((n & 64) ? 128 : 0)
                + (uint32_t)(((((n & 63) >> 3) ^ (k & 7)) & 7) * 16);
            ldsm_x4_t(b[2 * j][0], b[2 * j][1], b[2 * j + 1][0], b[2 * j + 1][1], addr);
        }
        #pragma unroll
        for (int mi = 0; mi < 4; mi++)
            #pragma unroll
            for (int nj = 0; nj < 8; nj++)
                mma16816(acc[mi][nj], a[mi], b[nj]);
    };

    // prologue: fill buffer 0
    load_A_half(0, 0); store_A_half(0, 0);
    load_A_half(0, 1); store_A_half(0, 1);
    load_B_half(0, 0); store_B_half(0, 0);
    load_B_half(0, 1); store_B_half(0, 1);
    __syncthreads();

    #pragma unroll 1
    for (int t = 0; t < cnt; t++) {
        const int buf = t & 1, nb = (t + 1) & 1;
        const bool more = (t + 1 < cnt);
        // half 0 loads for t+1 issued before compute -> latency hidden under MMAs
        if (more) { load_A_half(t + 1, 0); load_B_half(t + 1, 0); }
        compute1(buf, 0);
        compute1(buf, 1);
        if (more) {
            store_A_half(nb, 0); store_B_half(nb, 0);   // nb not read this iter: safe
            load_A_half(t + 1, 1); load_B_half(t + 1, 1);
        }
        compute1(buf, 2);
        compute1(buf, 3);
        if (more) { store_A_half(nb, 1); store_B_half(nb, 1); }
        __syncthreads();
    }

    // epilogue: write split-K partials (deterministic)
    const int row0 = lane >> 2;
    const int col0 = (lane & 3) * 2;
    float* dst = &g_partial[(size_t)chunk * B_DIM * K_OUT];
    #pragma unroll
    for (int mi = 0; mi < 4; mi++) {
        #pragma unroll
        for (int nj = 0; nj < 8; nj++) {
            const size_t m = mbase + m0w + mi * 16 + row0;
            const int n = n0w + nj * 8 + col0;
            float2 v0 = make_float2(acc[mi][nj][0], acc[mi][nj][1]);
            float2 v1 = make_float2(acc[mi][nj][2], acc[mi][nj][3]);
            *reinterpret_cast<float2*>(dst + m * K_OUT + n) = v0;
            *reinterpret_cast<float2*>(dst + (m + 8) * K_OUT + n) = v1;
        }
    }
}

__global__ void reduce_kernel(float* __restrict__ out) {
    const int i = blockIdx.x * blockDim.x + threadIdx.x;  // < 16384 (float4 granules)
    const float4* p = reinterpret_cast<const float4*>(g_partial) + i;
    float4 s = make_float4(0.f, 0.f, 0.f, 0.f);
    #pragma unroll 12
    for (int c = 0; c < SPLITK; c++) {
        float4 v = p[(size_t)c * (B_DIM * K_OUT / 4)];
        s.x += v.x; s.y += v.y; s.z += v.z; s.w += v.w;
    }
    reinterpret_cast<float4*>(out)[i] = s;
}

extern "C" void kernel_launch(void* const* d_in, const int* in_sizes, int n_in,
                              void* d_out, int out_size) {
    const float* X = (const float*)d_in[0];
    const float* W = (const float*)d_in[1];
    float* out = (float*)d_out;

    cudaFuncSetAttribute(gemm_splitk_kernel,
                         cudaFuncAttributeMaxDynamicSharedMemorySize, SMEM_BYTES);
    gemm_splitk_kernel<<<SPLITK * (B_DIM / M_TILE), NTHREADS, SMEM_BYTES>>>(X, W);
    reduce_kernel<<<(B_DIM * K_OUT / 4) / 256, 256>>>(out);
}

// round 8
// speedup vs baseline: 1.1354x; 1.0070x over previous
#include <cuda_runtime.h>
#include <cuda_fp16.h>
#include <cstdint>

// Problem: out[b,k] = sum_ij X[b,ij] * W[ij,k];  B=512, ij=1M, k=128
#define IJ_DIM   1048576
#define B_DIM    512
#define K_OUT    128
#define M_TILE   256
#define KR_TILE  64
#define SPLITK   72
#define K_TILES_TOTAL (IJ_DIM / KR_TILE)      // 16384
#define NTHREADS 512
// A fp16 tile 256x64 = 32KB, B fp16 64x128 = 16KB
#define STAGE_BYTES 49152
#define SMEM_BYTES  (2 * STAGE_BYTES)         // 96KB double buffered

// split-K partials [SPLITK][B_DIM][K_OUT] (~18.9 MB device scratch, no allocs)
__device__ float g_partial[(size_t)SPLITK * B_DIM * K_OUT];

__device__ __forceinline__ uint32_t smem_u32(const void* p) {
    uint32_t a;
    asm("{ .reg .u64 t; cvta.to.shared.u64 t, %1; cvt.u32.u64 %0, t; }" : "=r"(a) : "l"(p));
    return a;
}
__device__ __forceinline__ uint32_t packh2(float f0, float f1) {
    __half2 h = __floats2half2_rn(f0, f1);
    return *reinterpret_cast<uint32_t*>(&h);
}
__device__ __forceinline__ void ldsm_x4(uint32_t& r0, uint32_t& r1, uint32_t& r2, uint32_t& r3,
                                        uint32_t addr) {
    asm volatile("ldmatrix.sync.aligned.m8n8.x4.shared.b16 {%0,%1,%2,%3}, [%4];"
                 : "=r"(r0), "=r"(r1), "=r"(r2), "=r"(r3) : "r"(addr));
}
__device__ __forceinline__ void ldsm_x4_t(uint32_t& r0, uint32_t& r1, uint32_t& r2, uint32_t& r3,
                                          uint32_t addr) {
    asm volatile("ldmatrix.sync.aligned.m8n8.x4.trans.shared.b16 {%0,%1,%2,%3}, [%4];"
                 : "=r"(r0), "=r"(r1), "=r"(r2), "=r"(r3) : "r"(addr));
}
__device__ __forceinline__ void mma16816(float* c, const uint32_t* a, const uint32_t* b) {
    asm volatile(
        "mma.sync.aligned.m16n8k16.row.col.f32.f16.f16.f32 "
        "{%0,%1,%2,%3}, {%4,%5,%6,%7}, {%8,%9}, {%0,%1,%2,%3};"
        : "+f"(c[0]), "+f"(c[1]), "+f"(c[2]), "+f"(c[3])
        : "r"(a[0]), "r"(a[1]), "r"(a[2]), "r"(a[3]), "r"(b[0]), "r"(b[1]));
}

__global__ void __launch_bounds__(NTHREADS, 1)
gemm_splitk_kernel(const float* __restrict__ X, const float* __restrict__ W)
{
    extern __shared__ __align__(1024) char smem[];
    const int tid  = threadIdx.x;
    const int lane = tid & 31;
    const int wid  = tid >> 5;

    const int mtile = blockIdx.x & 1;
    const int chunk = blockIdx.x >> 1;
    // 16384 k-tiles over 72 chunks: first 40 get 228, rest 227
    const int base_tile = chunk * 227 + (chunk < 40 ? chunk : 40);
    const int cnt       = 227 + (chunk < 40 ? 1 : 0);
    const size_t mbase  = (size_t)mtile * M_TILE;
    const size_t kb0    = (size_t)base_tile * KR_TILE;

    const uint32_t smem_base = smem_u32(smem);

    // ---- load mappings (coalesced float4, 512 threads) ----
    // A: 256 rows x 64 cols fp32; pass p covers rows p*64..p*64+63
    const int ar_row = tid >> 3;          // 0..63
    const int ar_c8  = (tid & 7) * 8;     // 0..56
    // B: 64 k-rows x 128 n; pass p covers k p*16..p*16+15
    const int br_k  = tid >> 5;           // 0..15
    const int br_n4 = (tid & 31) * 4;     // 0..124

    // ---- swizzled store offsets (constant per thread; pass strides are mult of 8 rows) ----
    const uint32_t a_st_c = (uint32_t)(((tid & 7) ^ (ar_row & 7)) & 7) * 16;
    const uint32_t b_st_c = (uint32_t)((br_n4 & 64) ? 128 : 0)
                          + (uint32_t)(((((br_n4 & 63) >> 3) ^ (br_k & 7)) & 7) * 16)
                          + (uint32_t)((br_n4 & 7) * 2);

    // ---- warp compute tile: 8(m) x 2(n) warps, each 32m x 64n ----
    const int m0w = (wid & 7) * 32;
    const int n0w = (wid >> 3) * 64;

    const int lrow  = (lane & 7) + ((lane >> 3) & 1) * 8;
    const int lksel = lane >> 4;
    const int lnsel = (lane >> 4) * 8;

    float acc[2][8][4];
    #pragma unroll
    for (int i = 0; i < 2; i++)
        #pragma unroll
        for (int j = 0; j < 8; j++)
            #pragma unroll
            for (int c = 0; c < 4; c++) acc[i][j][c] = 0.f;

    float4 ar[4];   // A half: 2 row-passes x 2 float4 (16 regs)
    float4 wr[2];   // B half: 2 k-passes x 1 float4 (8 regs)

    auto load_A_half = [&](int t, int h) {
        const size_t kb = kb0 + (size_t)t * KR_TILE;
        #pragma unroll
        for (int p = 0; p < 2; p++) {
            const float* xp = X + (mbase + (h * 2 + p) * 64 + ar_row) * (size_t)IJ_DIM + kb + ar_c8;
            ar[p * 2]     = *reinterpret_cast<const float4*>(xp);
            ar[p * 2 + 1] = *reinterpret_cast<const float4*>(xp + 4);
        }
    };
    auto load_B_half = [&](int t, int h) {
        const size_t kb = kb0 + (size_t)t * KR_TILE;
        #pragma unroll
        for (int p = 0; p < 2; p++)
            wr[p] = *reinterpret_cast<const float4*>(
                W + (kb + (h * 2 + p) * 16 + br_k) * (size_t)K_OUT + br_n4);
    };
    auto store_A_half = [&](int buf, int h) {
        char* As = smem + buf * STAGE_BYTES;
        #pragma unroll
        for (int p = 0; p < 2; p++) {
            const float* f = reinterpret_cast<const float*>(&ar[p * 2]);
            uint4 v;
            v.x = packh2(f[0], f[1]); v.y = packh2(f[2], f[3]);
            v.z = packh2(f[4], f[5]); v.w = packh2(f[6], f[7]);
            *reinterpret_cast<uint4*>(
                As + (uint32_t)((h * 2 + p) * 64 + ar_row) * 128 + a_st_c) = v;
        }
    };
    auto store_B_half = [&](int buf, int h) {
        char* Bs = smem + buf * STAGE_BYTES + 32768;
        #pragma unroll
        for (int p = 0; p < 2; p++) {
            uint2 v;
            v.x = packh2(wr[p].x, wr[p].y); v.y = packh2(wr[p].z, wr[p].w);
            *reinterpret_cast<uint2*>(
                Bs + (uint32_t)((h * 2 + p) * 16 + br_k) * 256 + b_st_c) = v;
        }
    };

    auto compute1 = [&](int buf, int ks) {
        const uint32_t As = smem_base + buf * STAGE_BYTES;
        const uint32_t Bs = As + 32768;
        uint32_t a[2][4];
        #pragma unroll
        for (int mi = 0; mi < 2; mi++) {
            const int row = m0w + mi * 16 + lrow;
            const uint32_t addr = As + (uint32_t)row * 128
                + (uint32_t)((((ks * 2 + lksel) ^ (lrow & 7)) & 7) * 16);
            ldsm_x4(a[mi][0], a[mi][1], a[mi][2], a[mi][3], addr);
        }
        // B in two n-halves to bound fragment registers
        #pragma unroll
        for (int nh = 0; nh < 2; nh++) {
            uint32_t b[4][2];
            #pragma unroll
            for (int j = 0; j < 2; j++) {
                const int k = ks * 16 + lrow;
                const int n = n0w + nh * 32 + j * 16 + lnsel;
                const uint32_t addr = Bs + (uint32_t)k * 256
                    + (uint32_t)((n & 64) ? 128 : 0)
                    + (uint32_t)(((((n & 63) >> 3) ^ (k & 7)) & 7) * 16);
                ldsm_x4_t(b[2 * j][0], b[2 * j][1], b[2 * j + 1][0], b[2 * j + 1][1], addr);
            }
            #pragma unroll
            for (int mi = 0; mi < 2; mi++)
                #pragma unroll
                for (int nj = 0; nj < 4; nj++)
                    mma16816(acc[mi][nh * 4 + nj], a[mi], b[nj]);
        }
    };

    // prologue: fill buffer 0
    load_A_half(0, 0); load_B_half(0, 0);
    store_A_half(0, 0); store_B_half(0, 0);
    load_A_half(0, 1); load_B_half(0, 1);
    store_A_half(0, 1); store_B_half(0, 1);
    __syncthreads();

    #pragma unroll 1
    for (int t = 0; t < cnt; t++) {
        const int buf = t & 1, nb = (t + 1) & 1;
        const bool more = (t + 1 < cnt);
        if (more) { load_A_half(t + 1, 0); load_B_half(t + 1, 0); }
        compute1(buf, 0);
        compute1(buf, 1);
        if (more) {
            store_A_half(nb, 0); store_B_half(nb, 0);   // nb is free this iter
            load_A_half(t + 1, 1); load_B_half(t + 1, 1);
        }
        compute1(buf, 2);
        compute1(buf, 3);
        if (more) { store_A_half(nb, 1); store_B_half(nb, 1); }
        __syncthreads();
    }

    // epilogue: write split-K partials (deterministic)
    const int row0 = lane >> 2;
    const int col0 = (lane & 3) * 2;
    float* dst = &g_partial[(size_t)chunk * B_DIM * K_OUT];
    #pragma unroll
    for (int mi = 0; mi < 2; mi++) {
        #pragma unroll
        for (int nj = 0; nj < 8; nj++) {
            const size_t m = mbase + m0w + mi * 16 + row0;
            const int n = n0w + nj * 8 + col0;
            float2 v0 = make_float2(acc[mi][nj][0], acc[mi][nj][1]);
            float2 v1 = make_float2(acc[mi][nj][2], acc[mi][nj][3]);
            *reinterpret_cast<float2*>(dst + m * K_OUT + n) = v0;
            *reinterpret_cast<float2*>(dst + (m + 8) * K_OUT + n) = v1;
        }
    }
}

__global__ void reduce_kernel(float* __restrict__ out) {
    const int idx = blockIdx.x * blockDim.x + threadIdx.x;  // < 65536
    float s = 0.f;
    #pragma unroll 8
    for (int c = 0; c < SPLITK; c++)
        s += g_partial[(size_t)c * (B_DIM * K_OUT) + idx];
    out[idx] = s;
}

extern "C" void kernel_launch(void* const* d_in, const int* in_sizes, int n_in,
                              void* d_out, int out_size) {
    const float* X = (const float*)d_in[0];
    const float* W = (const float*)d_in[1];
    float* out = (float*)d_out;

    cudaFuncSetAttribute(gemm_splitk_kernel,
                         cudaFuncAttributeMaxDynamicSharedMemorySize, SMEM_BYTES);
    gemm_splitk_kernel<<<SPLITK * (B_DIM / M_TILE), NTHREADS, SMEM_BYTES>>>(X, W);
    reduce_kernel<<<(B_DIM * K_OUT) / 256, 256>>>(out);
}